// round 12
// baseline (speedup 1.0000x reference)
#include <cuda_runtime.h>

// Problem constants (fixed by setup_inputs)
#define B_ 16
#define T_ 8192
#define D_ 64
#define D4 (D_ / 4)       // 16 float4 columns
#define CHUNK 16          // == WINDOW
#define CPT 2             // chunks per thread -> 32 timesteps per thread
#define TPT (CHUNK * CPT) // 32
#define YDIM 4
#define BLOCK_T (TPT * YDIM) // 128 timesteps per block

__device__ __forceinline__ float fexp2(float x) {
    float y; asm("ex2.approx.ftz.f32 %0, %1;" : "=f"(y) : "f"(x)); return y;
}
__device__ __forceinline__ float flog2(float x) {
    float y; asm("lg2.approx.ftz.f32 %0, %1;" : "=f"(y) : "f"(x)); return y;
}

// out[b,t,d] = -(1/5) * log( sum_{k=0..15} exp(-5 * x[b, max(t-k,0), d]) )
// Chunked prefix/suffix decomposition, streaming stores, in-place suffix.
// R12: FLOAT4 vectorization over D (16 lanes x float4 = 64 floats/row).
// R11 audit showed the ~21us plateau is LSU ISSUE cost: LDG.64=4cyc +
// STG.64=7.75cyc per warp-instr ~= 22.6K cyc/SM (58% of elapsed).
// LDG.128/STG.128 halve the instruction count per byte -> ~7.5K cyc saved.
__global__ __launch_bounds__(64, 8) void always_kernel(
    const float* __restrict__ lower,
    const float* __restrict__ upper,
    float* __restrict__ out)
{
    const float C1 = -7.2134752044448169f;   // -5 * log2(e)
    const float C2 = -0.13862943611198906f;  // -ln(2) / 5

    const int d4 = threadIdx.x;              // 0..15 float4 column (coalesced)
    const int b  = blockIdx.y;               // 0..15
    const int tr = blockIdx.z;               // 0: lower, 1: upper
    const int t0 = blockIdx.x * BLOCK_T + threadIdx.y * TPT;

    const float* src = tr ? upper : lower;
    float*       dst = out + (size_t)tr * ((size_t)B_ * T_ * D_);

    const float4* col  = (const float4*)src + (size_t)b * T_ * D4 + d4;
    float4*       ocol = (float4*)dst      + (size_t)b * T_ * D4 + d4;

    // Halo suffix sums of the 15 preceding (index-clamped) timesteps.
    // Clamp to 0 reproduces h0's replication of x[:,0,:] exactly
    // (duplicates ARE counted in the logsumexp, matching the reference).
    float4 sf[16];                           // slots 1..15 used
    {
        #pragma unroll
        for (int k = 1; k < 16; k++) {
            int t = t0 - 16 + k;
            if (t < 0) t = 0;
            float4 v = col[t * D4];
            sf[k].x = fexp2(v.x * C1);
            sf[k].y = fexp2(v.y * C1);
            sf[k].z = fexp2(v.z * C1);
            sf[k].w = fexp2(v.w * C1);
        }
        #pragma unroll
        for (int k = 14; k >= 1; k--) {
            sf[k].x += sf[k + 1].x;
            sf[k].y += sf[k + 1].y;
            sf[k].z += sf[k + 1].z;
            sf[k].w += sf[k + 1].w;
        }
    }

    #pragma unroll 1
    for (int c = 0; c < CPT; c++) {
        const int tc = t0 + c * CHUNK;

        // 16 independent LDG.128 -> 512B per warp per issue slot.
        float4 v[16];
        #pragma unroll
        for (int r = 0; r < 16; r++) v[r] = col[(tc + r) * D4];

        // Fused pass: window_sum = prefix_cur[r] + suffix_prev[r+1].
        // e is written into sf[r] IN PLACE (sf[r] dead after step r-1).
        float4 p = make_float4(0.f, 0.f, 0.f, 0.f);
        #pragma unroll
        for (int r = 0; r < 16; r++) {
            float4 e;
            e.x = fexp2(v[r].x * C1);
            e.y = fexp2(v[r].y * C1);
            e.z = fexp2(v[r].z * C1);
            e.w = fexp2(v[r].w * C1);
            p.x += e.x; p.y += e.y; p.z += e.z; p.w += e.w;
            float4 w = p;
            if (r < 15) {
                w.x += sf[r + 1].x;
                w.y += sf[r + 1].y;
                w.z += sf[r + 1].z;
                w.w += sf[r + 1].w;
            }
            float4 o;
            o.x = flog2(w.x) * C2;
            o.y = flog2(w.y) * C2;
            o.z = flog2(w.z) * C2;
            o.w = flog2(w.w) * C2;
            __stcs(&ocol[(tc + r) * D4], o);   // STG.128, evict-first
            if (r >= 1) sf[r] = e;             // e[0] never needed again
        }

        // Reverse-accumulate in place -> suffix sums for the next chunk.
        if (c + 1 < CPT) {
            #pragma unroll
            for (int k = 14; k >= 1; k--) {
                sf[k].x += sf[k + 1].x;
                sf[k].y += sf[k + 1].y;
                sf[k].z += sf[k + 1].z;
                sf[k].w += sf[k + 1].w;
            }
        }
    }
}

extern "C" void kernel_launch(void* const* d_in, const int* in_sizes, int n_in,
                              void* d_out, int out_size) {
    const float* lower = (const float*)d_in[0];
    const float* upper = (const float*)d_in[1];
    float* out = (float*)d_out;

    dim3 block(D4, YDIM);                  // 16 x 4 = 64 threads
    dim3 grid(T_ / BLOCK_T, B_, 2);        // 64 x 16 x 2 = 2048 blocks
    always_kernel<<<grid, block>>>(lower, upper, out);
}

// round 13
// speedup vs baseline: 1.4003x; 1.4003x over previous
#include <cuda_runtime.h>

// Problem constants (fixed by setup_inputs)
#define B_ 16
#define T_ 8192
#define D_ 64
#define D2 (D_ / 2)       // 32 float2 columns
#define CHUNK 16          // == WINDOW
#define CPT 2             // chunks per thread -> 32 timesteps per thread
#define TPT (CHUNK * CPT) // 32
#define YDIM 4
#define BLOCK_T (TPT * YDIM) // 128 timesteps per block

__device__ __forceinline__ float fexp2(float x) {
    float y; asm("ex2.approx.ftz.f32 %0, %1;" : "=f"(y) : "f"(x)); return y;
}
__device__ __forceinline__ float flog2(float x) {
    float y; asm("lg2.approx.ftz.f32 %0, %1;" : "=f"(y) : "f"(x)); return y;
}

// out[b,t,d] = -(1/5) * log( sum_{k=0..15} exp(-5 * x[b, max(t-k,0), d]) )
// Chunked prefix/suffix decomposition, float2 over D, streaming stores,
// in-place suffix construction.
// R13: R11's warp supply (55 warps/SM offered: CPT=2, 64 regs) in R8's
// block shape (2048 x 128-thread blocks — the config with ZERO
// harness-vs-ncu replay gap). R12 proved any config <24 warps/SM loses;
// R11 proved CPT=2 @ 64 regs gives the best raw kernel time (19.26us).
__global__ __launch_bounds__(128, 8) void always_kernel(
    const float* __restrict__ lower,
    const float* __restrict__ upper,
    float* __restrict__ out)
{
    const float C1 = -7.2134752044448169f;   // -5 * log2(e)
    const float C2 = -0.13862943611198906f;  // -ln(2) / 5

    const int d2 = threadIdx.x;              // 0..31 float2 column (coalesced)
    const int b  = blockIdx.y;               // 0..15
    const int tr = blockIdx.z;               // 0: lower, 1: upper
    const int t0 = blockIdx.x * BLOCK_T + threadIdx.y * TPT;

    const float* src = tr ? upper : lower;
    float*       dst = out + (size_t)tr * ((size_t)B_ * T_ * D_);

    const float2* col  = (const float2*)src + (size_t)b * T_ * D2 + d2;
    float2*       ocol = (float2*)dst      + (size_t)b * T_ * D2 + d2;

    // Halo suffix sums of the 15 preceding (index-clamped) timesteps.
    // Clamp to 0 reproduces h0's replication of x[:,0,:] exactly
    // (duplicates ARE counted in the logsumexp, matching the reference).
    float sfx[16], sfy[16];                  // slots 1..15 used
    {
        float2 vh[16];
        #pragma unroll
        for (int k = 1; k < 16; k++) {
            int t = t0 - 16 + k;
            if (t < 0) t = 0;
            vh[k] = col[t * D2];
        }
        #pragma unroll
        for (int k = 1; k < 16; k++) {
            sfx[k] = fexp2(vh[k].x * C1);
            sfy[k] = fexp2(vh[k].y * C1);
        }
        #pragma unroll
        for (int k = 14; k >= 1; k--) { sfx[k] += sfx[k + 1]; sfy[k] += sfy[k + 1]; }
    }

    #pragma unroll 1
    for (int c = 0; c < CPT; c++) {
        const int tc = t0 + c * CHUNK;

        // 16 independent LDG.64 -> high MLP, 256B per warp per slot.
        float2 v[16];
        #pragma unroll
        for (int r = 0; r < 16; r++) v[r] = col[(tc + r) * D2];

        // Fused pass: window_sum = prefix_cur[r] + suffix_prev[r+1].
        // e[r] is written into sf[r] IN PLACE: sf[r] was last read at step
        // r-1, so the slot is dead by the time step r overwrites it.
        float px = 0.0f, py = 0.0f;
        #pragma unroll
        for (int r = 0; r < 16; r++) {
            float ex = fexp2(v[r].x * C1);
            float ey = fexp2(v[r].y * C1);
            px += ex;
            py += ey;
            float wx = (r < 15) ? (px + sfx[r + 1]) : px;
            float wy = (r < 15) ? (py + sfy[r + 1]) : py;
            float2 o;
            o.x = flog2(wx) * C2;
            o.y = flog2(wy) * C2;
            __stcs(&ocol[(tc + r) * D2], o);   // evict-first: outputs never re-read
            if (r >= 1) { sfx[r] = ex; sfy[r] = ey; }  // e[0] never needed again
        }

        // Reverse-accumulate in place -> suffix sums for the next chunk.
        if (c + 1 < CPT) {
            #pragma unroll
            for (int k = 14; k >= 1; k--) { sfx[k] += sfx[k + 1]; sfy[k] += sfy[k + 1]; }
        }
    }
}

extern "C" void kernel_launch(void* const* d_in, const int* in_sizes, int n_in,
                              void* d_out, int out_size) {
    const float* lower = (const float*)d_in[0];
    const float* upper = (const float*)d_in[1];
    float* out = (float*)d_out;

    dim3 block(D2, YDIM);                  // 32 x 4 = 128 threads
    dim3 grid(T_ / BLOCK_T, B_, 2);        // 64 x 16 x 2 = 2048 blocks
    always_kernel<<<grid, block>>>(lower, upper, out);
}